// round 1
// baseline (speedup 1.0000x reference)
#include <cuda_runtime.h>
#include <cuda_bf16.h>

// ---------------------------------------------------------------------------
// PatchTokenizer: entropy-masked multi-scale patch gather.
// B=32, C=3, IMG=512, fine ps=16 (32x32 grid), coarse ps=32 (16x16 grid).
// Output layout (float32, tuple order, concatenated):
//   [0)                 sel16  : N16 * 3*16*16
//   [OFF1)              full32 : N32 * 4*3*16*16
//   [OFF2)              sel32  : N32 * 3*16*16
//   [OFF_f16)           flat16 : 32768   (0/1)
//   [OFF_f32)           flat32 : 8192    (0/1)
//   [OFF_mask)          output_mask : 32 + N16 + N32  (-1 / 1 / 2)
//   [OFF_seq)           seqlens : 32
//   [OFF_cu)            cu_seqlens : 33
//   [OFF_max)           max_seqlen : 1
//   [OFF_frac)          retained_frac : 1
// ---------------------------------------------------------------------------

#define NCOARSE 8192    // 32 * 16 * 16
#define NFINE   32768   // 32 * 32 * 32

__device__ int d_m32[NCOARSE];    // coarse keep mask (entropy < 7.2)
__device__ int d_idx32[NCOARSE];  // exclusive prefix of m32
__device__ int d_idx16[NFINE];    // exclusive prefix of fine keep mask
__device__ int d_off[2];          // {OFF1/4, OFF2/4} in float4 units

// ---------------- Kernel 1: per-coarse-patch histogram entropy -------------
__global__ void __launch_bounds__(256) entropy_kernel(
    const float* __restrict__ img, const float* __restrict__ mean,
    const float* __restrict__ stdv)
{
    __shared__ int hist[512];
    const int p = blockIdx.x;          // coarse patch id
    const int t = threadIdx.x;         // 256 threads
    hist[t] = 0; hist[t + 256] = 0;
    __syncthreads();

    const int b  = p >> 8;
    const int ic = (p >> 4) & 15;
    const int jc = p & 15;
    const float m0 = mean[0], m1 = mean[1], m2 = mean[2];
    const float s0 = stdv[0], s1 = stdv[1], s2 = stdv[2];
    const float* base = img + (size_t)b * (3 * 512 * 512);

    #pragma unroll
    for (int it = 0; it < 4; it++) {
        int l = t + it * 256;              // 0..1023 within 32x32 patch
        int r = l >> 5, s = l & 31;
        int off = (ic * 32 + r) * 512 + (jc * 32 + s);
        float v0 = base[off];
        float v1 = base[262144 + off];
        float v2 = base[524288 + off];
        float u0 = fminf(fmaxf((v0 * s0 + m0) * 255.0f, 0.0f), 255.0f);
        float u1 = fminf(fmaxf((v1 * s1 + m1) * 255.0f, 0.0f), 255.0f);
        float u2 = fminf(fmaxf((v2 * s2 + m2) * 255.0f, 0.0f), 255.0f);
        float gray = u0 * 0.2989f + u1 * 0.587f + u2 * 0.114f;
        int bin = (int)(gray * 2.0f);
        bin = max(0, min(bin, 511));
        atomicAdd(&hist[bin], 1);
    }
    __syncthreads();

    float e = 0.0f;
    #pragma unroll
    for (int i = 0; i < 2; i++) {
        float pr = (float)hist[t + i * 256] * (1.0f / 1024.0f);
        e -= pr * log2f(pr + 1e-10f);
    }
    // block reduce (256 threads)
    #pragma unroll
    for (int d = 16; d > 0; d >>= 1) e += __shfl_down_sync(0xffffffffu, e, d);
    __shared__ float we[8];
    int lane = t & 31, wid = t >> 5;
    if (lane == 0) we[wid] = e;
    __syncthreads();
    if (t == 0) {
        float s = 0.0f;
        #pragma unroll
        for (int i = 0; i < 8; i++) s += we[i];
        d_m32[p] = (s < 7.2f) ? 1 : 0;
    }
}

// ---------------- block-wide exclusive scan (blockDim = 1024) --------------
__device__ __forceinline__ int block_excl_scan(int v, int& tot)
{
    __shared__ int ws[32];
    __shared__ int stot;
    const int lane = threadIdx.x & 31, wid = threadIdx.x >> 5;
    int x = v;
    #pragma unroll
    for (int d = 1; d < 32; d <<= 1) {
        int y = __shfl_up_sync(0xffffffffu, x, d);
        if (lane >= d) x += y;
    }
    if (lane == 31) ws[wid] = x;
    __syncthreads();
    if (wid == 0) {
        int w = ws[lane];
        int xx = w;
        #pragma unroll
        for (int d = 1; d < 32; d <<= 1) {
            int y = __shfl_up_sync(0xffffffffu, xx, d);
            if (lane >= d) xx += y;
        }
        ws[lane] = xx - w;              // exclusive warp-prefix
        if (lane == 31) stot = xx;
    }
    __syncthreads();
    tot = stot;
    int r = ws[wid] + x - v;
    __syncthreads();                    // allow shared reuse by next call
    return r;
}

// ---------------- Kernel 2: scans + scalar/bookkeeping outputs -------------
__global__ void __launch_bounds__(1024) scan_kernel(float* __restrict__ out)
{
    const int t = threadIdx.x;          // 1024 threads, 1 block
    __shared__ int sh_n32[32];
    __shared__ int sh_cu[33];

    // coarse scan: 8 elems/thread
    int cv[8]; int csum = 0;
    #pragma unroll
    for (int i = 0; i < 8; i++) { cv[i] = d_m32[t * 8 + i]; csum += cv[i]; }
    int tot32;
    int cex = block_excl_scan(csum, tot32);
    {
        int e = cex;
        #pragma unroll
        for (int i = 0; i < 8; i++) { d_idx32[t * 8 + i] = e; e += cv[i]; }
    }

    // fine scan: thread t owns one fine row (batch t>>5, row t&31, 32 cols)
    const int fb = t >> 5, fi = t & 31;
    const int cbase = fb * 256 + (fi >> 1) * 16;
    int mrow[16]; int msum = 0;
    #pragma unroll
    for (int j = 0; j < 16; j++) { mrow[j] = d_m32[cbase + j]; msum += mrow[j]; }
    int ftot;
    int fex = block_excl_scan(32 - 2 * msum, ftot);
    {
        int e = fex;
        #pragma unroll
        for (int j = 0; j < 32; j++) { d_idx16[t * 32 + j] = e; e += 1 - mrow[j >> 1]; }
    }
    __syncthreads();   // d_idx32 / d_idx16 visible to the whole block

    const int N32 = tot32;
    const int N16 = NFINE - 4 * N32;

    if (t < 32) {
        int start = d_idx32[t * 256];
        int end   = (t == 31) ? N32 : d_idx32[(t + 1) * 256];
        sh_n32[t] = end - start;
    }
    __syncthreads();
    if (t == 0) {
        int acc = 0; sh_cu[0] = 0;
        for (int b = 0; b < 32; b++) { acc += 1025 - 3 * sh_n32[b]; sh_cu[b + 1] = acc; }
        d_off[0] = N16 * 192;                 // full32 start, float4 units
        d_off[1] = N16 * 192 + N32 * 768;     // sel32 start, float4 units
    }
    __syncthreads();

    const int sumseq   = sh_cu[32];           // = 32 + N16 + N32
    const int OFF1     = N16 * 768;
    const int OFF2     = OFF1 + N32 * 3072;
    const int OFF_f16  = OFF2 + N32 * 768;
    const int OFF_f32  = OFF_f16 + NFINE;
    const int OFF_mask = OFF_f32 + NCOARSE;
    const int OFF_seq  = OFF_mask + sumseq;
    const int OFF_cu   = OFF_seq + 32;
    const int OFF_max  = OFF_cu + 33;
    const int OFF_frac = OFF_max + 1;

    // flat16 + output_mask "1" entries
    for (int q = t; q < NFINE; q += 1024) {
        int qb = q >> 10, qi = (q >> 5) & 31, qj = q & 31;
        int m = d_m32[qb * 256 + (qi >> 1) * 16 + (qj >> 1)];
        out[OFF_f16 + q] = (float)(1 - m);
        if (!m) {
            int keptBefore = qb * 1024 - 4 * d_idx32[qb * 256];
            out[OFF_mask + sh_cu[qb] + 1 + (d_idx16[q] - keptBefore)] = 1.0f;
        }
    }
    // flat32 + output_mask "2" entries
    for (int p = t; p < NCOARSE; p += 1024) {
        int m = d_m32[p];
        out[OFF_f32 + p] = (float)m;
        if (m) {
            int pb = p >> 8;
            int n16b = 1024 - 4 * sh_n32[pb];
            out[OFF_mask + sh_cu[pb] + 1 + n16b + (d_idx32[p] - d_idx32[pb * 256])] = 2.0f;
        }
    }
    if (t < 32) {
        out[OFF_mask + sh_cu[t]] = -1.0f;
        out[OFF_seq + t] = (float)(1025 - 3 * sh_n32[t]);
        out[OFF_cu + t]  = (float)sh_cu[t];
    }
    if (t == 0) {
        out[OFF_cu + 32] = (float)sh_cu[32];
        int mx = 0;
        for (int b = 0; b < 32; b++) mx = max(mx, 1025 - 3 * sh_n32[b]);
        out[OFF_max]  = (float)mx;
        out[OFF_frac] = (float)sumseq / 32768.0f;
    }
}

// ---------------- Kernel 3: data-dependent patch gathers -------------------
__global__ void __launch_bounds__(256) gather_kernel(
    const float* __restrict__ img, float* __restrict__ out)
{
    const int p = blockIdx.x;          // coarse patch id
    const int t = threadIdx.x;         // 256 threads
    const int b  = p >> 8;
    const int ic = (p >> 4) & 15;
    const int jc = p & 15;
    const float4* base4 = (const float4*)(img + (size_t)b * (3 * 512 * 512));
    float4* out4 = (float4*)out;

    if (!d_m32[p]) {
        // 4 retained fine patches -> sel16 slots. 768 float4 per coarse.
        #pragma unroll
        for (int it = 0; it < 3; it++) {
            int e = t + it * 256;
            int k = e / 192, w = e - k * 192;       // w = c*64 + r*4 + s4
            int c = w >> 6, r = (w >> 2) & 15, s4 = w & 3;
            int di = k >> 1, dj = k & 1;
            int y = ic * 32 + di * 16 + r;
            float4 v = base4[c * 65536 + y * 128 + jc * 8 + dj * 4 + s4];
            int q = (b << 10) + ((2 * ic + di) << 5) + (2 * jc + dj);
            out4[(size_t)d_idx16[q] * 192 + w] = v;
        }
    } else {
        const int slot = d_idx32[p];
        // full32: same bytes, [k,c,16,16] layout; dest float4 = off + slot*768 + e
        const int o1 = d_off[0] + slot * 768;
        #pragma unroll
        for (int it = 0; it < 3; it++) {
            int e = t + it * 256;
            int k = e / 192, w = e - k * 192;
            int c = w >> 6, r = (w >> 2) & 15, s4 = w & 3;
            int di = k >> 1, dj = k & 1;
            int y = ic * 32 + di * 16 + r;
            float4 v = base4[c * 65536 + y * 128 + jc * 8 + dj * 4 + s4];
            out4[(size_t)o1 + e] = v;
        }
        // sel32: 2x2-mean downsampled 16x16 patch (exact bilinear at scale 0.5)
        if (t < 192) {
            int c = t >> 6, r = (t >> 2) & 15, s4 = t & 3;
            int y0 = ic * 32 + 2 * r;
            int xb = jc * 8 + 2 * s4;              // float4 index, covers 8 cols
            float4 a0 = base4[c * 65536 + y0 * 128 + xb];
            float4 a1 = base4[c * 65536 + y0 * 128 + xb + 1];
            float4 b0 = base4[c * 65536 + (y0 + 1) * 128 + xb];
            float4 b1 = base4[c * 65536 + (y0 + 1) * 128 + xb + 1];
            float4 o;
            o.x = 0.25f * (a0.x + a0.y + b0.x + b0.y);
            o.y = 0.25f * (a0.z + a0.w + b0.z + b0.w);
            o.z = 0.25f * (a1.x + a1.y + b1.x + b1.y);
            o.w = 0.25f * (a1.z + a1.w + b1.z + b1.w);
            out4[(size_t)d_off[1] + slot * 192 + t] = o;
        }
    }
}

// ---------------------------------------------------------------------------
extern "C" void kernel_launch(void* const* d_in, const int* in_sizes, int n_in,
                              void* d_out, int out_size)
{
    const float* img  = (const float*)d_in[0];
    const float* mean = (const float*)d_in[1];
    const float* stdv = (const float*)d_in[2];
    float* out = (float*)d_out;

    entropy_kernel<<<NCOARSE, 256>>>(img, mean, stdv);
    scan_kernel<<<1, 1024>>>(out);
    gather_kernel<<<NCOARSE, 256>>>(img, out);
}

// round 2
// speedup vs baseline: 1.1625x; 1.1625x over previous
#include <cuda_runtime.h>
#include <cuda_bf16.h>

// ---------------------------------------------------------------------------
// PatchTokenizer: entropy-masked multi-scale patch gather.
// B=32, C=3, IMG=512, fine ps=16 (32x32 grid), coarse ps=32 (16x16 grid).
// Output layout (float32, tuple order, concatenated):
//   sel16 | full32 | sel32 | flat16 | flat32 | output_mask | seqlens |
//   cu_seqlens | max_seqlen | retained_frac
// ---------------------------------------------------------------------------

#define NCOARSE 8192    // 32 * 16 * 16
#define NFINE   32768   // 32 * 32 * 32

__device__ int d_m32[NCOARSE];    // coarse keep mask (entropy < 7.2)
__device__ int d_idx32[NCOARSE];  // exclusive prefix of m32
__device__ int d_idx16[NFINE];    // exclusive prefix of fine keep mask
__device__ int d_off[5];          // {full32_f4, sel32_f4, OFF_f16, OFF_f32, OFF_mask}
__device__ int d_cu[33];          // per-batch cu_seqlens
__device__ int d_n32b[32];        // per-batch coarse kept count

// ---------------- Kernel 1: per-coarse-patch histogram entropy -------------
__global__ void __launch_bounds__(256) entropy_kernel(
    const float* __restrict__ img, const float* __restrict__ mean,
    const float* __restrict__ stdv)
{
    __shared__ int hist[512];
    const int p = blockIdx.x;          // coarse patch id
    const int t = threadIdx.x;         // 256 threads
    hist[t] = 0; hist[t + 256] = 0;
    __syncthreads();

    const int b  = p >> 8;
    const int ic = (p >> 4) & 15;
    const int jc = p & 15;
    const float m0 = mean[0], m1 = mean[1], m2 = mean[2];
    const float s0 = stdv[0], s1 = stdv[1], s2 = stdv[2];
    const float4* base4 = (const float4*)(img + (size_t)b * 786432);

    // thread -> (row r = t>>3, float4-col f4 = t&7): 32 rows x 8 f4 = 1024 px
    const int r  = t >> 3;
    const int f4 = t & 7;
    const int a  = (ic * 32 + r) * 128 + jc * 8 + f4;
    float4 v0 = base4[a];
    float4 v1 = base4[65536 + a];
    float4 v2 = base4[131072 + a];

    #pragma unroll
    for (int i = 0; i < 4; i++) {
        float x0 = (&v0.x)[i], x1 = (&v1.x)[i], x2 = (&v2.x)[i];
        float u0 = fminf(fmaxf((x0 * s0 + m0) * 255.0f, 0.0f), 255.0f);
        float u1 = fminf(fmaxf((x1 * s1 + m1) * 255.0f, 0.0f), 255.0f);
        float u2 = fminf(fmaxf((x2 * s2 + m2) * 255.0f, 0.0f), 255.0f);
        float gray = u0 * 0.2989f + u1 * 0.587f + u2 * 0.114f;
        int bin = (int)(gray * 2.0f);
        bin = max(0, min(bin, 511));
        atomicAdd(&hist[bin], 1);
    }
    __syncthreads();

    float e = 0.0f;
    #pragma unroll
    for (int i = 0; i < 2; i++) {
        float pr = (float)hist[t + i * 256] * (1.0f / 1024.0f);
        e -= pr * log2f(pr + 1e-10f);
    }
    #pragma unroll
    for (int d = 16; d > 0; d >>= 1) e += __shfl_down_sync(0xffffffffu, e, d);
    __shared__ float we[8];
    int lane = t & 31, wid = t >> 5;
    if (lane == 0) we[wid] = e;
    __syncthreads();
    if (t == 0) {
        float s = 0.0f;
        #pragma unroll
        for (int i = 0; i < 8; i++) s += we[i];
        d_m32[p] = (s < 7.2f) ? 1 : 0;
    }
}

// ---------------- block-wide exclusive scan (blockDim = 1024) --------------
__device__ __forceinline__ int block_excl_scan(int v, int& tot)
{
    __shared__ int ws[32];
    __shared__ int stot;
    const int lane = threadIdx.x & 31, wid = threadIdx.x >> 5;
    int x = v;
    #pragma unroll
    for (int d = 1; d < 32; d <<= 1) {
        int y = __shfl_up_sync(0xffffffffu, x, d);
        if (lane >= d) x += y;
    }
    if (lane == 31) ws[wid] = x;
    __syncthreads();
    if (wid == 0) {
        int w = ws[lane];
        int xx = w;
        #pragma unroll
        for (int d = 1; d < 32; d <<= 1) {
            int y = __shfl_up_sync(0xffffffffu, xx, d);
            if (lane >= d) xx += y;
        }
        ws[lane] = xx - w;              // exclusive warp-prefix
        if (lane == 31) stot = xx;
    }
    __syncthreads();
    tot = stot;
    int rr = ws[wid] + x - v;
    __syncthreads();                    // allow shared reuse by next call
    return rr;
}

// ---------------- Kernel 2: scans + scalar outputs (small now) -------------
__global__ void __launch_bounds__(1024) scan_kernel(float* __restrict__ out)
{
    const int t = threadIdx.x;          // 1024 threads, 1 block
    __shared__ int sh_n32[32];
    __shared__ int sh_cu[33];

    // coarse scan: 8 elems/thread
    int cv[8]; int csum = 0;
    #pragma unroll
    for (int i = 0; i < 8; i++) { cv[i] = d_m32[t * 8 + i]; csum += cv[i]; }
    int tot32;
    int cex = block_excl_scan(csum, tot32);
    {
        int e = cex;
        #pragma unroll
        for (int i = 0; i < 8; i++) { d_idx32[t * 8 + i] = e; e += cv[i]; }
    }

    // fine scan: thread t owns one fine row (batch t>>5, row t&31, 32 cols)
    const int fb = t >> 5, fi = t & 31;
    const int cbase = fb * 256 + (fi >> 1) * 16;
    int mrow[16]; int msum = 0;
    #pragma unroll
    for (int j = 0; j < 16; j++) { mrow[j] = d_m32[cbase + j]; msum += mrow[j]; }
    int ftot;
    int fex = block_excl_scan(32 - 2 * msum, ftot);
    {
        int e = fex;
        #pragma unroll
        for (int j = 0; j < 32; j++) { d_idx16[t * 32 + j] = e; e += 1 - mrow[j >> 1]; }
    }
    __syncthreads();   // d_idx32 visible to whole block

    const int N32 = tot32;
    const int N16 = NFINE - 4 * N32;

    if (t < 32) {
        int start = d_idx32[t * 256];
        int end   = (t == 31) ? N32 : d_idx32[(t + 1) * 256];
        sh_n32[t] = end - start;
    }
    __syncthreads();
    if (t == 0) {
        int acc = 0; sh_cu[0] = 0;
        for (int b = 0; b < 32; b++) { acc += 1025 - 3 * sh_n32[b]; sh_cu[b + 1] = acc; }
    }
    __syncthreads();

    const int sumseq   = sh_cu[32];           // = 32 + N16 + N32
    const int OFF1     = N16 * 768;
    const int OFF2     = OFF1 + N32 * 3072;
    const int OFF_f16  = OFF2 + N32 * 768;
    const int OFF_f32  = OFF_f16 + NFINE;
    const int OFF_mask = OFF_f32 + NCOARSE;
    const int OFF_seq  = OFF_mask + sumseq;
    const int OFF_cu   = OFF_seq + 32;
    const int OFF_max  = OFF_cu + 33;
    const int OFF_frac = OFF_max + 1;

    if (t < 32) {
        d_n32b[t] = sh_n32[t];
        d_cu[t]   = sh_cu[t];
        out[OFF_mask + sh_cu[t]] = -1.0f;
        out[OFF_seq + t] = (float)(1025 - 3 * sh_n32[t]);
        out[OFF_cu + t]  = (float)sh_cu[t];
    }
    if (t == 0) {
        d_cu[32] = sh_cu[32];
        d_off[0] = N16 * 192;                 // full32 start, float4 units
        d_off[1] = N16 * 192 + N32 * 768;     // sel32 start, float4 units
        d_off[2] = OFF_f16;
        d_off[3] = OFF_f32;
        d_off[4] = OFF_mask;
        out[OFF_cu + 32] = (float)sh_cu[32];
        int mx = 0;
        for (int b = 0; b < 32; b++) mx = max(mx, 1025 - 3 * sh_n32[b]);
        out[OFF_max]  = (float)mx;
        out[OFF_frac] = (float)sumseq / 32768.0f;
    }
}

// ---------------- Kernel 3: gathers + per-patch bookkeeping ----------------
__global__ void __launch_bounds__(256) gather_kernel(
    const float* __restrict__ img, float* __restrict__ out)
{
    const int p = blockIdx.x;          // coarse patch id
    const int t = threadIdx.x;         // 256 threads
    const int b  = p >> 8;
    const int ic = (p >> 4) & 15;
    const int jc = p & 15;
    const float4* base4 = (const float4*)(img + (size_t)b * 786432);
    float4* out4 = (float4*)out;
    const int m = d_m32[p];

    // thread -> sub-patch k (0..3), position w0 in [0,64): r=w0>>2, s4=w0&3
    const int k  = t >> 6;
    const int w0 = t & 63;
    const int r  = w0 >> 2, s4 = w0 & 3;
    const int di = k >> 1,  dj = k & 1;
    const int y  = ic * 32 + di * 16 + r;
    const int xs = jc * 8 + dj * 4 + s4;
    const int srcb = y * 128 + xs;

    if (!m) {
        const int q = (b << 10) + ((2 * ic + di) << 5) + (2 * jc + dj);
        const size_t dst = (size_t)d_idx16[q] * 192;
        #pragma unroll
        for (int c = 0; c < 3; c++)
            out4[dst + c * 64 + w0] = base4[c * 65536 + srcb];
    } else {
        const int slot = d_idx32[p];
        const size_t o1 = (size_t)d_off[0] + (size_t)slot * 768 + k * 192;
        #pragma unroll
        for (int c = 0; c < 3; c++)
            out4[o1 + c * 64 + w0] = base4[c * 65536 + srcb];

        // sel32: 2x2-mean downsampled 16x16 patch (bilinear at scale 0.5)
        if (t < 192) {
            int c2 = t >> 6, r2 = (t >> 2) & 15, s42 = t & 3;
            int y0 = ic * 32 + 2 * r2;
            int xb = jc * 8 + 2 * s42;
            float4 a0 = base4[c2 * 65536 + y0 * 128 + xb];
            float4 a1 = base4[c2 * 65536 + y0 * 128 + xb + 1];
            float4 b0 = base4[c2 * 65536 + (y0 + 1) * 128 + xb];
            float4 b1 = base4[c2 * 65536 + (y0 + 1) * 128 + xb + 1];
            float4 o;
            o.x = 0.25f * (a0.x + a0.y + b0.x + b0.y);
            o.y = 0.25f * (a0.z + a0.w + b0.z + b0.w);
            o.z = 0.25f * (a1.x + a1.y + b1.x + b1.y);
            o.w = 0.25f * (a1.z + a1.w + b1.z + b1.w);
            out4[(size_t)d_off[1] + (size_t)slot * 192 + t] = o;
        }
    }

    // ---- bookkeeping: flat16 / flat32 / output_mask (one thread per block)
    if (t == 0) {
        out[d_off[3] + p] = (float)m;            // flat32
        const int cu_b  = d_cu[b];
        const int b16s  = d_idx32[b << 8];       // coarse kept before batch b
        if (!m) {
            const int keptBefore = b * 1024 - 4 * b16s;
            #pragma unroll
            for (int kk = 0; kk < 4; kk++) {
                int ddi = kk >> 1, ddj = kk & 1;
                int q = (b << 10) + ((2 * ic + ddi) << 5) + (2 * jc + ddj);
                out[d_off[2] + q] = 1.0f;                               // flat16
                out[d_off[4] + cu_b + 1 + (d_idx16[q] - keptBefore)] = 1.0f;
            }
        } else {
            #pragma unroll
            for (int kk = 0; kk < 4; kk++) {
                int ddi = kk >> 1, ddj = kk & 1;
                int q = (b << 10) + ((2 * ic + ddi) << 5) + (2 * jc + ddj);
                out[d_off[2] + q] = 0.0f;                               // flat16
            }
            int n16b = 1024 - 4 * d_n32b[b];
            out[d_off[4] + cu_b + 1 + n16b + (d_idx32[p] - b16s)] = 2.0f;
        }
    }
}

// ---------------------------------------------------------------------------
extern "C" void kernel_launch(void* const* d_in, const int* in_sizes, int n_in,
                              void* d_out, int out_size)
{
    const float* img  = (const float*)d_in[0];
    const float* mean = (const float*)d_in[1];
    const float* stdv = (const float*)d_in[2];
    float* out = (float*)d_out;

    entropy_kernel<<<NCOARSE, 256>>>(img, mean, stdv);
    scan_kernel<<<1, 1024>>>(out);
    gather_kernel<<<NCOARSE, 256>>>(img, out);
}

// round 3
// speedup vs baseline: 1.1657x; 1.0028x over previous
#include <cuda_runtime.h>
#include <cuda_bf16.h>

// ---------------------------------------------------------------------------
// PatchTokenizer: entropy-masked multi-scale patch gather.
// B=32, C=3, IMG=512, fine ps=16 (32x32 grid), coarse ps=32 (16x16 grid).
// Output layout (float32, tuple order, concatenated):
//   sel16 | full32 | sel32 | flat16 | flat32 | output_mask | seqlens |
//   cu_seqlens | max_seqlen | retained_frac
// ---------------------------------------------------------------------------

#define NCOARSE 8192    // 32 * 16 * 16
#define NFINE   32768   // 32 * 32 * 32

__device__ int d_m32[NCOARSE];    // coarse keep mask (entropy < 7.2)
__device__ int d_idx32[NCOARSE];  // exclusive prefix of m32
__device__ int d_idx16[NFINE];    // exclusive prefix of fine keep mask
__device__ int d_off[5];          // {full32_f4, sel32_f4, OFF_f16, OFF_f32, OFF_mask}
__device__ int d_cu[33];          // per-batch cu_seqlens
__device__ int d_n32b[32];        // per-batch coarse kept count

// ---------------- Kernel 1: per-coarse-patch histogram entropy -------------
__global__ void __launch_bounds__(256) entropy_kernel(
    const float* __restrict__ img, const float* __restrict__ mean,
    const float* __restrict__ stdv)
{
    __shared__ int hist[512];
    const int p = blockIdx.x;          // coarse patch id
    const int t = threadIdx.x;         // 256 threads
    hist[t] = 0; hist[t + 256] = 0;
    __syncthreads();

    const int b  = p >> 8;
    const int ic = (p >> 4) & 15;
    const int jc = p & 15;
    // fold *255 into scale/bias: (x*s+m)*255 == x*(255 s) + (255 m)
    const float s0 = stdv[0] * 255.0f, s1 = stdv[1] * 255.0f, s2 = stdv[2] * 255.0f;
    const float m0 = mean[0] * 255.0f, m1 = mean[1] * 255.0f, m2 = mean[2] * 255.0f;
    const float4* base4 = (const float4*)(img + (size_t)b * 786432);

    // thread -> (row r = t>>3, float4-col f4 = t&7): 32 rows x 8 f4 = 1024 px
    const int r  = t >> 3;
    const int f4 = t & 7;
    const int a  = (ic * 32 + r) * 128 + jc * 8 + f4;
    float4 v0 = base4[a];
    float4 v1 = base4[65536 + a];
    float4 v2 = base4[131072 + a];

    #pragma unroll
    for (int i = 0; i < 4; i++) {
        float u0 = fminf(fmaxf(fmaf((&v0.x)[i], s0, m0), 0.0f), 255.0f);
        float u1 = fminf(fmaxf(fmaf((&v1.x)[i], s1, m1), 0.0f), 255.0f);
        float u2 = fminf(fmaxf(fmaf((&v2.x)[i], s2, m2), 0.0f), 255.0f);
        float gray = fmaf(u0, 0.2989f, fmaf(u1, 0.587f, u2 * 0.114f));
        int bin = (int)(gray * 2.0f);      // gray in [0, 254.98] -> bin in [0, 509]
        atomicAdd(&hist[bin], 1);
    }
    __syncthreads();

    // entropy: skip zero-count bins (their +eps term contributes ~3e-9 bits)
    float e = 0.0f;
    #pragma unroll
    for (int i = 0; i < 2; i++) {
        int c = hist[t + i * 256];
        if (c) {
            float pr = (float)c * (1.0f / 1024.0f);
            e -= pr * __log2f(pr + 1e-10f);   // single MUFU.LG2
        }
    }
    #pragma unroll
    for (int d = 16; d > 0; d >>= 1) e += __shfl_down_sync(0xffffffffu, e, d);
    __shared__ float we[8];
    int lane = t & 31, wid = t >> 5;
    if (lane == 0) we[wid] = e;
    __syncthreads();
    if (t == 0) {
        float s = 0.0f;
        #pragma unroll
        for (int i = 0; i < 8; i++) s += we[i];
        d_m32[p] = (s < 7.2f) ? 1 : 0;
    }
}

// ---------------- block-wide exclusive scan (blockDim = 1024) --------------
__device__ __forceinline__ int block_excl_scan(int v, int& tot)
{
    __shared__ int ws[32];
    __shared__ int stot;
    const int lane = threadIdx.x & 31, wid = threadIdx.x >> 5;
    int x = v;
    #pragma unroll
    for (int d = 1; d < 32; d <<= 1) {
        int y = __shfl_up_sync(0xffffffffu, x, d);
        if (lane >= d) x += y;
    }
    if (lane == 31) ws[wid] = x;
    __syncthreads();
    if (wid == 0) {
        int w = ws[lane];
        int xx = w;
        #pragma unroll
        for (int d = 1; d < 32; d <<= 1) {
            int y = __shfl_up_sync(0xffffffffu, xx, d);
            if (lane >= d) xx += y;
        }
        ws[lane] = xx - w;              // exclusive warp-prefix
        if (lane == 31) stot = xx;
    }
    __syncthreads();
    tot = stot;
    int rr = ws[wid] + x - v;
    __syncthreads();                    // allow shared reuse by next call
    return rr;
}

// ---------------- Kernel 2: scans + scalar outputs -------------------------
__global__ void __launch_bounds__(1024) scan_kernel(float* __restrict__ out)
{
    const int t = threadIdx.x;          // 1024 threads, 1 block
    __shared__ int sh_n32[32];
    __shared__ int sh_cu[33];

    // coarse scan: 8 elems/thread
    int cv[8]; int csum = 0;
    #pragma unroll
    for (int i = 0; i < 8; i++) { cv[i] = d_m32[t * 8 + i]; csum += cv[i]; }
    int tot32;
    int cex = block_excl_scan(csum, tot32);
    {
        int e = cex;
        #pragma unroll
        for (int i = 0; i < 8; i++) { d_idx32[t * 8 + i] = e; e += cv[i]; }
    }

    // fine scan: thread t owns one fine row (batch t>>5, row t&31, 32 cols)
    const int fb = t >> 5, fi = t & 31;
    const int cbase = fb * 256 + (fi >> 1) * 16;
    int mrow[16]; int msum = 0;
    #pragma unroll
    for (int j = 0; j < 16; j++) { mrow[j] = d_m32[cbase + j]; msum += mrow[j]; }
    int ftot;
    int fex = block_excl_scan(32 - 2 * msum, ftot);
    {
        int e = fex;
        #pragma unroll
        for (int j = 0; j < 32; j++) { d_idx16[t * 32 + j] = e; e += 1 - mrow[j >> 1]; }
    }
    __syncthreads();   // d_idx32 visible to whole block

    const int N32 = tot32;
    const int N16 = NFINE - 4 * N32;

    if (t < 32) {
        int start = d_idx32[t * 256];
        int end   = (t == 31) ? N32 : d_idx32[(t + 1) * 256];
        sh_n32[t] = end - start;
    }
    __syncthreads();
    if (t == 0) {
        int acc = 0; sh_cu[0] = 0;
        for (int b = 0; b < 32; b++) { acc += 1025 - 3 * sh_n32[b]; sh_cu[b + 1] = acc; }
    }
    __syncthreads();

    const int sumseq   = sh_cu[32];           // = 32 + N16 + N32
    const int OFF1     = N16 * 768;
    const int OFF2     = OFF1 + N32 * 3072;
    const int OFF_f16  = OFF2 + N32 * 768;
    const int OFF_f32  = OFF_f16 + NFINE;
    const int OFF_mask = OFF_f32 + NCOARSE;
    const int OFF_seq  = OFF_mask + sumseq;
    const int OFF_cu   = OFF_seq + 32;
    const int OFF_max  = OFF_cu + 33;
    const int OFF_frac = OFF_max + 1;

    if (t < 32) {
        d_n32b[t] = sh_n32[t];
        d_cu[t]   = sh_cu[t];
        out[OFF_mask + sh_cu[t]] = -1.0f;
        out[OFF_seq + t] = (float)(1025 - 3 * sh_n32[t]);
        out[OFF_cu + t]  = (float)sh_cu[t];
    }
    if (t == 0) {
        d_cu[32] = sh_cu[32];
        d_off[0] = N16 * 192;                 // full32 start, float4 units
        d_off[1] = N16 * 192 + N32 * 768;     // sel32 start, float4 units
        d_off[2] = OFF_f16;
        d_off[3] = OFF_f32;
        d_off[4] = OFF_mask;
        out[OFF_cu + 32] = (float)sh_cu[32];
        int mx = 0;
        for (int b = 0; b < 32; b++) mx = max(mx, 1025 - 3 * sh_n32[b]);
        out[OFF_max]  = (float)mx;
        out[OFF_frac] = (float)sumseq / 32768.0f;
    }
}

// ---------------- Kernel 3: gathers + per-patch bookkeeping ----------------
// 192 threads/block, each thread owns (c, w0) and loops the 4 sub-patches k:
// 4 independent load->store float4 chains per thread (deep MLP batch).
__global__ void __launch_bounds__(192) gather_kernel(
    const float* __restrict__ img, float* __restrict__ out)
{
    const int p = blockIdx.x;          // coarse patch id
    const int t = threadIdx.x;         // 192 threads
    const int b  = p >> 8;
    const int ic = (p >> 4) & 15;
    const int jc = p & 15;
    const float4* base4 = (const float4*)(img + (size_t)b * 786432);
    float4* out4 = (float4*)out;
    const int m = d_m32[p];

    const int c  = t >> 6;             // channel 0..2
    const int w0 = t & 63;             // r = w0>>2 (0..15), s4 = w0&3
    const int r  = w0 >> 2, s4 = w0 & 3;

    // batch the 4 sub-patch loads (independent -> MLP=4)
    float4 v[4];
    #pragma unroll
    for (int k = 0; k < 4; k++) {
        int di = k >> 1, dj = k & 1;
        int y  = ic * 32 + di * 16 + r;
        int xs = jc * 8 + dj * 4 + s4;
        v[k] = base4[c * 65536 + y * 128 + xs];
    }

    if (!m) {
        #pragma unroll
        for (int k = 0; k < 4; k++) {
            int di = k >> 1, dj = k & 1;
            int q = (b << 10) + ((2 * ic + di) << 5) + (2 * jc + dj);
            __stcs(&out4[(size_t)d_idx16[q] * 192 + c * 64 + w0], v[k]);
        }
    } else {
        const int slot = d_idx32[p];
        const size_t o1 = (size_t)d_off[0] + (size_t)slot * 768;
        #pragma unroll
        for (int k = 0; k < 4; k++)
            __stcs(&out4[o1 + k * 192 + c * 64 + w0], v[k]);

        // sel32: 2x2-mean downsampled 16x16 patch (bilinear at scale 0.5)
        {
            int y0 = ic * 32 + 2 * r;
            int xb = jc * 8 + 2 * s4;
            float4 a0 = base4[c * 65536 + y0 * 128 + xb];
            float4 a1 = base4[c * 65536 + y0 * 128 + xb + 1];
            float4 b0 = base4[c * 65536 + (y0 + 1) * 128 + xb];
            float4 b1 = base4[c * 65536 + (y0 + 1) * 128 + xb + 1];
            float4 o;
            o.x = 0.25f * (a0.x + a0.y + b0.x + b0.y);
            o.y = 0.25f * (a0.z + a0.w + b0.z + b0.w);
            o.z = 0.25f * (a1.x + a1.y + b1.x + b1.y);
            o.w = 0.25f * (a1.z + a1.w + b1.z + b1.w);
            __stcs(&out4[(size_t)d_off[1] + (size_t)slot * 192 + t], o);
        }
    }

    // ---- bookkeeping: flat16 / flat32 / output_mask (one thread per block)
    if (t == 0) {
        out[d_off[3] + p] = (float)m;            // flat32
        const int cu_b  = d_cu[b];
        const int b16s  = d_idx32[b << 8];       // coarse kept before batch b
        if (!m) {
            const int keptBefore = b * 1024 - 4 * b16s;
            #pragma unroll
            for (int kk = 0; kk < 4; kk++) {
                int ddi = kk >> 1, ddj = kk & 1;
                int q = (b << 10) + ((2 * ic + ddi) << 5) + (2 * jc + ddj);
                out[d_off[2] + q] = 1.0f;                               // flat16
                out[d_off[4] + cu_b + 1 + (d_idx16[q] - keptBefore)] = 1.0f;
            }
        } else {
            #pragma unroll
            for (int kk = 0; kk < 4; kk++) {
                int ddi = kk >> 1, ddj = kk & 1;
                int q = (b << 10) + ((2 * ic + ddi) << 5) + (2 * jc + ddj);
                out[d_off[2] + q] = 0.0f;                               // flat16
            }
            int n16b = 1024 - 4 * d_n32b[b];
            out[d_off[4] + cu_b + 1 + n16b + (d_idx32[p] - b16s)] = 2.0f;
        }
    }
}

// ---------------------------------------------------------------------------
extern "C" void kernel_launch(void* const* d_in, const int* in_sizes, int n_in,
                              void* d_out, int out_size)
{
    const float* img  = (const float*)d_in[0];
    const float* mean = (const float*)d_in[1];
    const float* stdv = (const float*)d_in[2];
    float* out = (float*)d_out;

    entropy_kernel<<<NCOARSE, 256>>>(img, mean, stdv);
    scan_kernel<<<1, 1024>>>(out);
    gather_kernel<<<NCOARSE, 192>>>(img, out);
}